// round 17
// baseline (speedup 1.0000x reference)
#include <cuda_runtime.h>
#include <math.h>

#define BATCH 2
#define HWd   192
#define HW2   (HWd*HWd)      // 36864
#define HGd   48
#define Ntok  (HGd*HGd)      // 2304
#define D2    256
#define VDdim 2048
#define NFtot 3
#define SELCAP 64
#define MAXU   128
#define NROWS (BATCH*NFtot*Ntok)

typedef unsigned long long u64;

// dynamic smem sizes for the GEMM kernels (A stored as duplicated u64 pairs)
#define ASD_BYTES (2*16*132*8)                       // 33792
#define CONV_SMEM (ASD_BYTES + 2*16*128*4)           // 50176
#define TT_SMEM   (ASD_BYTES + 2*16*132*4)           // 50688

// ---------------- scratch (device globals; no allocs allowed) ----------------
__device__ float g_buf1[(size_t)BATCH*384*HW2];
__device__ float g_buf2[(size_t)BATCH*384*HW2];
__device__ float g_buf3[(size_t)BATCH*512*HW2];
__device__ float g_buf4[(size_t)BATCH*512*Ntok];
__device__ float g_qtok[(size_t)BATCH*Ntok*D2];
__device__ float g_attn[(size_t)BATCH*NFtot*Ntok*Ntok];
__device__ float g_otok[(size_t)BATCH*NFtot*Ntok*VDdim];
__device__ int   g_selidx[(size_t)NROWS*SELCAP];
__device__ float g_selw  [(size_t)NROWS*SELCAP];
__device__ int   g_selcnt[NROWS];

// ---------------- packed fp32x2 primitives (Blackwell FFMA2) -----------------
__device__ __forceinline__ u64 dup2(float x) {
    u64 r;
    asm("mov.b64 %0, {%1, %1};" : "=l"(r) : "r"(__float_as_uint(x)));
    return r;
}
__device__ __forceinline__ void fma2(u64 &d, u64 a, u64 b) {
    asm("fma.rn.f32x2 %0, %1, %2, %3;" : "=l"(d) : "l"(a), "l"(b), "l"(d));
}
__device__ __forceinline__ float2 unpk(u64 v) {
    float lo, hi;
    asm("mov.b64 {%0, %1}, %2;" : "=f"(lo), "=f"(hi) : "l"(v));
    return make_float2(lo, hi);
}

// one k-step of the 8x8 fragment: 6 LDS.128 + 32 fma.f32x2, no dup movs
__device__ __forceinline__ void fma_step(
    const u64* __restrict__ As_k, const float* __restrict__ Bs_k,
    int tx, int ty, u64 acc[8][4])
{
    ulonglong2 aA = *(const ulonglong2*)(As_k + ty*4);
    ulonglong2 aB = *(const ulonglong2*)(As_k + ty*4 + 2);
    ulonglong2 aC = *(const ulonglong2*)(As_k + 64 + ty*4);
    ulonglong2 aD = *(const ulonglong2*)(As_k + 66 + ty*4);
    ulonglong2 bv0 = *(const ulonglong2*)(Bs_k + tx*4);
    ulonglong2 bv1 = *(const ulonglong2*)(Bs_k + 64 + tx*4);
    u64 aa[8] = {aA.x, aA.y, aB.x, aB.y, aC.x, aC.y, aD.x, aD.y};
    u64 bb[4] = {bv0.x, bv0.y, bv1.x, bv1.y};
    #pragma unroll
    for (int i = 0; i < 8; i++) {
        fma2(acc[i][0], aa[i], bb[0]);
        fma2(acc[i][1], aa[i], bb[1]);
        fma2(acc[i][2], aa[i], bb[2]);
        fma2(acc[i][3], aa[i], bb[3]);
    }
}

// =============================================================================
// double-buffered conv GEMM body (A duplicated in smem as u64)
// =============================================================================
__device__ __forceinline__ void gemm_db_conv2(
    const float* __restrict__ A, const float* __restrict__ Bbase, int K,
    u64 (* __restrict__ As)[16][132], float (* __restrict__ Bs)[16][128],
    int t, u64 acc[8][4])
{
    int arow = t >> 1, akq = (t & 1) * 8;
    int bk = t >> 4, bn = (t & 15) * 4;
    int tx = t & 15, ty = t >> 4;
    const float* Ap = A + (long)arow * K + akq;

    float4 a0 = *(const float4*)(Ap);
    float4 a1 = *(const float4*)(Ap + 4);
    const float* bs0 = Bbase + (long)bk * HW2;
    float4 b0 = *(const float4*)(bs0 + bn);
    float4 b1 = *(const float4*)(bs0 + bn + 64);
    As[0][akq+0][arow]=dup2(a0.x); As[0][akq+1][arow]=dup2(a0.y);
    As[0][akq+2][arow]=dup2(a0.z); As[0][akq+3][arow]=dup2(a0.w);
    As[0][akq+4][arow]=dup2(a1.x); As[0][akq+5][arow]=dup2(a1.y);
    As[0][akq+6][arow]=dup2(a1.z); As[0][akq+7][arow]=dup2(a1.w);
    *(float4*)&Bs[0][bk][bn]    = b0;
    *(float4*)&Bs[0][bk][bn+64] = b1;
    __syncthreads();
    int buf = 0;
    for (int k0 = 16; k0 <= K; k0 += 16) {
        if (k0 < K) {
            a0 = *(const float4*)(Ap + k0);
            a1 = *(const float4*)(Ap + k0 + 4);
            const float* bs2 = Bbase + (long)(k0 + bk) * HW2;
            b0 = *(const float4*)(bs2 + bn);
            b1 = *(const float4*)(bs2 + bn + 64);
        }
        #pragma unroll
        for (int kk = 0; kk < 16; kk++)
            fma_step(&As[buf][kk][0], &Bs[buf][kk][0], tx, ty, acc);
        if (k0 < K) {
            int nb = buf ^ 1;
            As[nb][akq+0][arow]=dup2(a0.x); As[nb][akq+1][arow]=dup2(a0.y);
            As[nb][akq+2][arow]=dup2(a0.z); As[nb][akq+3][arow]=dup2(a0.w);
            As[nb][akq+4][arow]=dup2(a1.x); As[nb][akq+5][arow]=dup2(a1.y);
            As[nb][akq+6][arow]=dup2(a1.z); As[nb][akq+7][arow]=dup2(a1.w);
            *(float4*)&Bs[nb][bk][bn]    = b0;
            *(float4*)&Bs[nb][bk][bn+64] = b1;
            __syncthreads();
            buf = nb;
        }
    }
}

// =============================================================================
// double-buffered TT GEMM body (A duplicated in smem as u64)
// =============================================================================
__device__ __forceinline__ void gemm_db_tt2(
    const float* __restrict__ Abase, const float* __restrict__ Bbase, int K,
    u64 (* __restrict__ As)[16][132], float (* __restrict__ Bs)[16][132],
    int t, u64 acc[8][4])
{
    int row = t >> 1, kq = (t & 1) * 8;
    int tx = t & 15, ty = t >> 4;
    const float* Ap = Abase + (long)row * K + kq;
    const float* Bp = Bbase + (long)row * K + kq;

    float4 a0 = *(const float4*)(Ap);
    float4 a1 = *(const float4*)(Ap + 4);
    float4 b0 = *(const float4*)(Bp);
    float4 b1 = *(const float4*)(Bp + 4);
    As[0][kq+0][row]=dup2(a0.x); As[0][kq+1][row]=dup2(a0.y);
    As[0][kq+2][row]=dup2(a0.z); As[0][kq+3][row]=dup2(a0.w);
    As[0][kq+4][row]=dup2(a1.x); As[0][kq+5][row]=dup2(a1.y);
    As[0][kq+6][row]=dup2(a1.z); As[0][kq+7][row]=dup2(a1.w);
    Bs[0][kq+0][row]=b0.x; Bs[0][kq+1][row]=b0.y; Bs[0][kq+2][row]=b0.z; Bs[0][kq+3][row]=b0.w;
    Bs[0][kq+4][row]=b1.x; Bs[0][kq+5][row]=b1.y; Bs[0][kq+6][row]=b1.z; Bs[0][kq+7][row]=b1.w;
    __syncthreads();
    int buf = 0;
    for (int k0 = 16; k0 <= K; k0 += 16) {
        if (k0 < K) {
            a0 = *(const float4*)(Ap + k0);
            a1 = *(const float4*)(Ap + k0 + 4);
            b0 = *(const float4*)(Bp + k0);
            b1 = *(const float4*)(Bp + k0 + 4);
        }
        #pragma unroll
        for (int kk = 0; kk < 16; kk++)
            fma_step(&As[buf][kk][0], &Bs[buf][kk][0], tx, ty, acc);
        if (k0 < K) {
            int nb = buf ^ 1;
            As[nb][kq+0][row]=dup2(a0.x); As[nb][kq+1][row]=dup2(a0.y);
            As[nb][kq+2][row]=dup2(a0.z); As[nb][kq+3][row]=dup2(a0.w);
            As[nb][kq+4][row]=dup2(a1.x); As[nb][kq+5][row]=dup2(a1.y);
            As[nb][kq+6][row]=dup2(a1.z); As[nb][kq+7][row]=dup2(a1.w);
            Bs[nb][kq+0][row]=b0.x; Bs[nb][kq+1][row]=b0.y; Bs[nb][kq+2][row]=b0.z; Bs[nb][kq+3][row]=b0.w;
            Bs[nb][kq+4][row]=b1.x; Bs[nb][kq+5][row]=b1.y; Bs[nb][kq+6][row]=b1.z; Bs[nb][kq+7][row]=b1.w;
            __syncthreads();
            buf = nb;
        }
    }
}

__device__ __forceinline__ void gemm128_store2(
    float* __restrict__ Crow, const float* __restrict__ bias,
    int t, u64 acc[8][4], long ldc)
{
    int tx = t & 15, ty = t >> 4;
    #pragma unroll
    for (int i = 0; i < 8; i++) {
        int m = (i < 4) ? (ty*4 + i) : (64 + ty*4 + i - 4);
        float bv = bias ? bias[m] : 0.f;
        float2 p0 = unpk(acc[i][0]), p1 = unpk(acc[i][1]);
        float2 p2 = unpk(acc[i][2]), p3 = unpk(acc[i][3]);
        float4 o0 = {p0.x+bv, p0.y+bv, p1.x+bv, p1.y+bv};
        float4 o1 = {p2.x+bv, p2.y+bv, p3.x+bv, p3.y+bv};
        *(float4*)&Crow[(long)m*ldc + tx*4]      = o0;
        *(float4*)&Crow[(long)m*ldc + 64 + tx*4] = o1;
    }
}

// stage A
__global__ void __launch_bounds__(256,2) gemm_stageA(
    const float* __restrict__ x,
    const float* __restrict__ qk_w, const float* __restrict__ qk_b,
    const float* __restrict__ v_w,  const float* __restrict__ v_b)
{
    extern __shared__ char dsm[];
    u64   (*As)[16][132] = (u64(*)[16][132])dsm;
    float (*Bs)[16][128] = (float(*)[16][128])(dsm + ASD_BYTES);
    int n0 = blockIdx.x * 128, y = blockIdx.y, b = blockIdx.z;
    int t = threadIdx.x;
    u64 acc[8][4] = {};
    const float* A   = (y < 2) ? (qk_w + (long)y*128*128) : v_w;
    const float* bia = (y < 2) ? (qk_b + y*128)           : v_b;
    int cch          = (y < 2) ? (y*128)                  : 256;
    gemm_db_conv2(A, x + (long)b*128*HW2 + n0, 128, As, Bs, t, acc);
    gemm128_store2(g_buf1 + ((long)b*384 + cch) * HW2 + n0, bia, t, acc, HW2);
}

// stage C
__global__ void __launch_bounds__(256,2) gemm_stageC(
    const float* __restrict__ q2_w, const float* __restrict__ q2_b,
    const float* __restrict__ k2_w, const float* __restrict__ k2_b)
{
    extern __shared__ char dsm[];
    u64   (*As)[16][132] = (u64(*)[16][132])dsm;
    float (*Bs)[16][128] = (float(*)[16][128])(dsm + ASD_BYTES);
    int n0 = blockIdx.x * 128, y = blockIdx.y, b = blockIdx.z;
    int t = threadIdx.x;
    u64 acc[8][4] = {};
    const float* A   = (y < 2) ? (q2_w + (long)y*128*128) : (k2_w + (long)(y-2)*128*128);
    const float* bia = (y < 2) ? (q2_b + y*128)           : (k2_b + (y-2)*128);
    const float* Bbase = g_buf2 + ((long)b*384 + ((y < 2) ? 0 : 128)) * HW2 + n0;
    gemm_db_conv2(A, Bbase, 128, As, Bs, t, acc);
    gemm128_store2(g_buf3 + ((long)b*512 + y*128) * HW2 + n0, bia, t, acc, HW2);
}

// attention GEMM
__global__ void __launch_bounds__(256,2) attn_gemm2(
    const float* __restrict__ kc, const float* __restrict__ knew)
{
    extern __shared__ char dsm[];
    u64   (*As)[16][132] = (u64(*)[16][132])dsm;
    float (*Bs)[16][132] = (float(*)[16][132])(dsm + ASD_BYTES);
    int z = blockIdx.z; int b = z / NFtot, f = z % NFtot;
    const float* Qp = g_qtok + (long)b * Ntok * D2;
    const float* Kp = (f < 2) ? (kc   + ((long)(b*2 + f)) * Ntok * D2)
                              : (knew + ((long)(b*2 + 1)) * Ntok * D2);
    int m0 = blockIdx.y * 128, n0 = blockIdx.x * 128;
    int t = threadIdx.x;
    int tx = t & 15, ty = t >> 4;
    u64 acc[8][4] = {};
    gemm_db_tt2(Qp + (long)m0 * D2, Kp + (long)n0 * D2, D2, As, Bs, t, acc);
    float* Cp = g_attn + (long)z * Ntok * Ntok;
    #pragma unroll
    for (int i = 0; i < 8; i++) {
        int m = (i < 4) ? (ty*4 + i) : (64 + ty*4 + i - 4);
        float2 p0 = unpk(acc[i][0]), p1 = unpk(acc[i][1]);
        float2 p2 = unpk(acc[i][2]), p3 = unpk(acc[i][3]);
        float4 o0 = {p0.x, p0.y, p1.x, p1.y};
        float4 o1 = {p2.x, p2.y, p3.x, p3.y};
        *(float4*)&Cp[(long)(m0+m)*Ntok + n0 + tx*4]      = o0;
        *(float4*)&Cp[(long)(m0+m)*Ntok + n0 + 64 + tx*4] = o1;
    }
}

// proj 1x1 GEMM with fused window de-permute gather
__global__ void __launch_bounds__(256,2) proj_gemm2(
    const float* __restrict__ W, const float* __restrict__ bias,
    float* __restrict__ Out)
{
    extern __shared__ char dsm[];
    u64   (*As)[16][132] = (u64(*)[16][132])dsm;
    float (*Bs)[16][132] = (float(*)[16][132])(dsm + ASD_BYTES);
    int z  = blockIdx.z;
    int n0 = blockIdx.x * 128;
    int t = threadIdx.x;
    int tx = t & 15, ty = t >> 4;
    u64 acc[8][4] = {};
    int row = t >> 1;
    int p = n0 + row;
    int h = p / HWd, w = p % HWd;
    int token = (h % HGd) * HGd + (w % HGd);
    int vbase = ((h / HGd) * 4 + (w / HGd)) * 128;
    // B rows are per-pixel 128-float vectors in g_otok; A rows are W rows.
    const float* Ap = W + (long)row * 128 + (t & 1) * 8;
    const float* Bp = g_otok + ((long)z * Ntok + token) * VDdim + vbase + (t & 1) * 8;
    gemm_db_tt2(Ap - (long)row * 128 - (t & 1) * 8 + 0, Bp - (t & 1) * 8 - 0, 0, As, Bs, t, acc); // placeholder never used
    (void)Ap; (void)Bp;
    // NOTE: proj uses a custom inline body because B rows come from per-pixel
    // gathered pointers; re-implemented below.
    ;
    #pragma unroll
    for (int i = 0; i < 8; i++) { (void)i; }
    // -- real body --
    {
        int kq = (t & 1) * 8;
        const float* Awp = W + (long)row * 128 + kq;
        const float* Bwp = g_otok + ((long)z * Ntok + token) * VDdim + vbase + kq;
        float4 a0 = *(const float4*)(Awp);
        float4 a1 = *(const float4*)(Awp + 4);
        float4 b0 = *(const float4*)(Bwp);
        float4 b1 = *(const float4*)(Bwp + 4);
        As[0][kq+0][row]=dup2(a0.x); As[0][kq+1][row]=dup2(a0.y);
        As[0][kq+2][row]=dup2(a0.z); As[0][kq+3][row]=dup2(a0.w);
        As[0][kq+4][row]=dup2(a1.x); As[0][kq+5][row]=dup2(a1.y);
        As[0][kq+6][row]=dup2(a1.z); As[0][kq+7][row]=dup2(a1.w);
        Bs[0][kq+0][row]=b0.x; Bs[0][kq+1][row]=b0.y; Bs[0][kq+2][row]=b0.z; Bs[0][kq+3][row]=b0.w;
        Bs[0][kq+4][row]=b1.x; Bs[0][kq+5][row]=b1.y; Bs[0][kq+6][row]=b1.z; Bs[0][kq+7][row]=b1.w;
        __syncthreads();
        int buf = 0;
        for (int k0 = 16; k0 <= 128; k0 += 16) {
            if (k0 < 128) {
                a0 = *(const float4*)(Awp + k0);
                a1 = *(const float4*)(Awp + k0 + 4);
                b0 = *(const float4*)(Bwp + k0);
                b1 = *(const float4*)(Bwp + k0 + 4);
            }
            #pragma unroll
            for (int kk = 0; kk < 16; kk++)
                fma_step(&As[buf][kk][0], &Bs[buf][kk][0], tx, ty, acc);
            if (k0 < 128) {
                int nb = buf ^ 1;
                As[nb][kq+0][row]=dup2(a0.x); As[nb][kq+1][row]=dup2(a0.y);
                As[nb][kq+2][row]=dup2(a0.z); As[nb][kq+3][row]=dup2(a0.w);
                As[nb][kq+4][row]=dup2(a1.x); As[nb][kq+5][row]=dup2(a1.y);
                As[nb][kq+6][row]=dup2(a1.z); As[nb][kq+7][row]=dup2(a1.w);
                Bs[nb][kq+0][row]=b0.x; Bs[nb][kq+1][row]=b0.y; Bs[nb][kq+2][row]=b0.z; Bs[nb][kq+3][row]=b0.w;
                Bs[nb][kq+4][row]=b1.x; Bs[nb][kq+5][row]=b1.y; Bs[nb][kq+6][row]=b1.z; Bs[nb][kq+7][row]=b1.w;
                __syncthreads();
                buf = nb;
            }
        }
    }
    #pragma unroll
    for (int i = 0; i < 8; i++) {
        int m = (i < 4) ? (ty*4 + i) : (64 + ty*4 + i - 4);
        float bv = bias[m];
        float2 p0 = unpk(acc[i][0]), p1 = unpk(acc[i][1]);
        float2 p2 = unpk(acc[i][2]), p3 = unpk(acc[i][3]);
        float4 o0 = {p0.x+bv, p0.y+bv, p1.x+bv, p1.y+bv};
        float4 o1 = {p2.x+bv, p2.y+bv, p3.x+bv, p3.y+bv};
        *(float4*)&Out[((long)z*128 + m)*HW2 + n0 + tx*4]      = o0;
        *(float4*)&Out[((long)z*128 + m)*HW2 + n0 + 64 + tx*4] = o1;
    }
}

// ---------------- depthwise 3x3 pad1, 4 pixels/thread -------------------------
__global__ void __launch_bounds__(256) dw3x3v(
    const float* __restrict__ qk_dw_w, const float* __restrict__ qk_dw_b,
    const float* __restrict__ v_dw_w,  const float* __restrict__ v_dw_b)
{
    int idx = blockIdx.x * 256 + threadIdx.x;
    const int NQ = BATCH*384*HW2/4;
    if (idx >= NQ) return;
    int qw = idx % (HWd/4);
    int h  = (idx / (HWd/4)) % HWd;
    int ch = (idx / (HW2/4)) % 384;
    int b  = idx / (384*HW2/4);
    int w0 = qw * 4;

    const float* wgt; float bv;
    if (ch < 256) { wgt = qk_dw_w + ch*9;        bv = qk_dw_b[ch]; }
    else          { wgt = v_dw_w  + (ch-256)*9;  bv = v_dw_b[ch-256]; }
    float k0=wgt[0],k1=wgt[1],k2=wgt[2],k3=wgt[3],k4=wgt[4],k5=wgt[5],k6=wgt[6],k7=wgt[7],k8=wgt[8];

    const float* in = g_buf1 + ((long)(b*384 + ch)) * HW2;
    float r[3][6];
    #pragma unroll
    for (int ky = 0; ky < 3; ky++) {
        int y = h + ky - 1;
        if ((unsigned)y >= (unsigned)HWd) {
            #pragma unroll
            for (int j = 0; j < 6; j++) r[ky][j] = 0.f;
        } else {
            const float* rp = in + (long)y * HWd + w0;
            float4 c = *(const float4*)rp;
            r[ky][1] = c.x; r[ky][2] = c.y; r[ky][3] = c.z; r[ky][4] = c.w;
            r[ky][0] = (w0 > 0)        ? rp[-1] : 0.f;
            r[ky][5] = (w0 + 4 < HWd)  ? rp[4]  : 0.f;
        }
    }
    float4 o;
    float* op = (float*)&o;
    #pragma unroll
    for (int j = 0; j < 4; j++) {
        op[j] = bv
              + k0*r[0][j] + k1*r[0][j+1] + k2*r[0][j+2]
              + k3*r[1][j] + k4*r[1][j+1] + k5*r[1][j+2]
              + k6*r[2][j] + k7*r[2][j+1] + k8*r[2][j+2];
    }
    *(float4*)&g_buf2[(long)idx*4] = o;
}

// ---------------- depthwise 4x4 stride4 pad1 ----------------------------------
__global__ void dw4x4(const float* __restrict__ q2_dw_w, const float* __restrict__ q2_dw_b,
                      const float* __restrict__ k2_dw_w, const float* __restrict__ k2_dw_b)
{
    int idx = blockIdx.x * 256 + threadIdx.x;
    if (idx >= BATCH*512*Ntok) return;
    int t  = idx % Ntok;
    int ch = (idx / Ntok) % 512;
    int b  = idx / (512*Ntok);
    int oy = t / HGd, ox = t % HGd;
    const float* wgt; float bv;
    if (ch < 256) { wgt = q2_dw_w + ch*16;       bv = q2_dw_b[ch]; }
    else          { wgt = k2_dw_w + (ch-256)*16; bv = k2_dw_b[ch-256]; }
    const float* in = g_buf3 + ((long)(b*512 + ch)) * HW2;
    float s = bv;
    #pragma unroll
    for (int ky = 0; ky < 4; ky++) {
        int y = oy*4 - 1 + ky;
        if ((unsigned)y >= (unsigned)HWd) continue;
        #pragma unroll
        for (int kx = 0; kx < 4; kx++) {
            int x = ox*4 - 1 + kx;
            if ((unsigned)x >= (unsigned)HWd) continue;
            s += wgt[ky*4+kx] * in[y*HWd + x];
        }
    }
    g_buf4[idx] = s;
}

// ---------------- l2 normalize + token-major q/k (shfl reductions) ------------
__global__ void __launch_bounds__(256) norm_qk(float* __restrict__ kout,
                                               const float* __restrict__ temp)
{
    int token = blockIdx.x, b = blockIdx.y, d = threadIdx.x;
    int lane = d & 31, wid = d >> 5;
    float qv = g_buf4[((long)b*512 + d)       * Ntok + token];
    float kv = g_buf4[((long)b*512 + 256 + d) * Ntok + token];
    __shared__ float wsumq[8], wsumk[8];
    __shared__ float qinv_s, kinv_s;
    float sq = qv*qv, sk = kv*kv;
    #pragma unroll
    for (int o = 16; o > 0; o >>= 1) {
        sq += __shfl_xor_sync(0xffffffffu, sq, o);
        sk += __shfl_xor_sync(0xffffffffu, sk, o);
    }
    if (lane == 0) { wsumq[wid] = sq; wsumk[wid] = sk; }
    __syncthreads();
    if (d < 32) {
        float tq = (lane < 8) ? wsumq[lane] : 0.f;
        float tk = (lane < 8) ? wsumk[lane] : 0.f;
        #pragma unroll
        for (int o = 4; o > 0; o >>= 1) {
            tq += __shfl_xor_sync(0xffffffffu, tq, o);
            tk += __shfl_xor_sync(0xffffffffu, tk, o);
        }
        if (lane == 0) {
            qinv_s = (*temp) / fmaxf(sqrtf(tq), 1e-12f);
            kinv_s = 1.f / fmaxf(sqrtf(tk), 1e-12f);
        }
    }
    __syncthreads();
    g_qtok[((long)b*Ntok + token) * D2 + d] = qv * qinv_s;
    kout  [((long)(b*2 + 1)*Ntok + token) * D2 + d] = kv * kinv_s;
}

// ---------------- build v_new: smem-transposed (coalesced both sides) ---------
__global__ void __launch_bounds__(256) build_vnew_t(float* __restrict__ vout)
{
    int hi = blockIdx.x;
    int pp = blockIdx.y;
    int b  = blockIdx.z;
    int p1 = pp >> 2, p2 = pp & 3;
    int tid = threadIdx.x;
    __shared__ float ts[48][129];

    const float* src = g_buf2 + ((long)(b*384 + 256)) * HW2
                       + (long)(p1*HGd + hi) * HWd + p2*HGd;
    for (int i = tid; i < 128*48; i += 256) {
        int c = i / 48, wi = i - c*48;
        ts[wi][c] = src[(long)c * HW2 + wi];
    }
    __syncthreads();
    float* dst = vout + ((long)(b*2 + 1)*Ntok + hi*HGd) * VDdim + p1*512 + p2*128;
    for (int i = tid; i < 48*32; i += 256) {
        int wi = i >> 5, c4 = (i & 31) * 4;
        float4 v = make_float4(ts[wi][c4], ts[wi][c4+1], ts[wi][c4+2], ts[wi][c4+3]);
        *(float4*)&dst[(long)wi * VDdim + c4] = v;
    }
}

// =============================================================================
// sparse_select4: 4 rows per block (64-thread warp-aligned groups)
// =============================================================================
__global__ void __launch_bounds__(256) sparse_select4()
{
    int f = blockIdx.y, b = blockIdx.z;
    int z = b*NFtot + f;
    int tid = threadIdx.x;
    int g = tid >> 6, lt = tid & 63;
    int n = blockIdx.x * 4 + g;
    int rowid = z * Ntok + n;
    const float* arow = g_attn + (long)rowid * Ntok;
    int ny = n / HGd, nx = n % HGd;

    __shared__ float candv[4][64][5];
    __shared__ float bkth[4], bmax[4], bsum[4];
    __shared__ int   nnz[4];
    __shared__ int   sidx[4][SELCAP];
    __shared__ float sval[4][SELCAP];

    if (lt == 0) nnz[g] = 0;

    float t5v[5] = {-INFINITY,-INFINITY,-INFINITY,-INFINITY,-INFINITY};
    int   t5i[5] = {0,0,0,0,0};
    for (int m4 = lt*4; m4 < Ntok; m4 += 256) {
        float4 v4 = *(const float4*)&arow[m4];
        float vv[4] = {v4.x, v4.y, v4.z, v4.w};
        #pragma unroll
        for (int u = 0; u < 4; u++) {
            float v = vv[u];
            if (v > t5v[4]) {
                t5v[4] = v; t5i[4] = m4 + u;
                #pragma unroll
                for (int i = 4; i > 0; i--)
                    if (t5v[i] > t5v[i-1]) {
                        float tv = t5v[i-1]; t5v[i-1] = t5v[i]; t5v[i] = tv;
                        int   ti = t5i[i-1]; t5i[i-1] = t5i[i]; t5i[i] = ti;
                    }
            }
        }
    }
    #pragma unroll
    for (int i = 0; i < 5; i++) candv[g][lt][i] = t5v[i];
    __syncthreads();

    if (lt < 32) {
        float l5[5] = {-INFINITY,-INFINITY,-INFINITY,-INFINITY,-INFINITY};
        const float* cp = &candv[g][lt*2][0];
        #pragma unroll
        for (int i = 0; i < 10; i++) {
            float v = cp[i];
            if (v > l5[4]) {
                l5[4] = v;
                #pragma unroll
                for (int j = 4; j > 0; j--)
                    if (l5[j] > l5[j-1]) { float tmp = l5[j-1]; l5[j-1] = l5[j]; l5[j] = tmp; }
            }
        }
        float thr = INFINITY;
        #pragma unroll
        for (int r = 0; r < 5; r++) {
            float lm = -INFINITY;
            #pragma unroll
            for (int i = 0; i < 5; i++) {
                float v = l5[i];
                if (v < thr && v > lm) lm = v;
            }
            #pragma unroll
            for (int o = 16; o > 0; o >>= 1)
                lm = fmaxf(lm, __shfl_xor_sync(0xffffffffu, lm, o));
            thr = lm;
        }
        if (lt == 0) bkth[g] = thr;
    }
    __syncthreads();
    float kth = bkth[g];

    if (lt < 41) {
        int r = lt, dy = 0;
        for (int d = -4; d <= 4; d++) {
            int sz = 9 - 2*abs(d);
            if (r < sz) { dy = d; break; }
            r -= sz;
        }
        int dx = r - (4 - abs(dy));
        int my = ny + dy, mx = nx + dx;
        if ((unsigned)my < (unsigned)HGd && (unsigned)mx < (unsigned)HGd) {
            int m = my*HGd + mx;
            float a = arow[m];
            float v = a * ((a >= kth) ? 2.f : 1.f);
            if (v != 0.f) {
                int pos = atomicAdd(&nnz[g], 1);
                sidx[g][pos] = m; sval[g][pos] = v;
            }
        }
    }
    #pragma unroll
    for (int i = 0; i < 5; i++) {
        float v = t5v[i];
        if (v >= kth && v != 0.f) {
            int m = t5i[i];
            int my = m / HGd, mx = m % HGd;
            if (abs(ny - my) + abs(nx - mx) > 4) {
                int pos = atomicAdd(&nnz[g], 1);
                sidx[g][pos] = m; sval[g][pos] = v;
            }
        }
    }
    __syncthreads();
    int cnt = min(nnz[g], SELCAP);

    if (lt < 32) {
        float mx = -INFINITY;
        for (int e = lt; e < cnt; e += 32) mx = fmaxf(mx, sval[g][e]);
        #pragma unroll
        for (int o = 16; o > 0; o >>= 1)
            mx = fmaxf(mx, __shfl_xor_sync(0xffffffffu, mx, o));
        if (lt == 0) bmax[g] = mx;
    }
    __syncthreads();
    float mxv = bmax[g];
    if (lt < cnt) sval[g][lt] = expf(sval[g][lt] - mxv);
    __syncthreads();
    if (lt < 32) {
        float s = 0.f;
        for (int e = lt; e < cnt; e += 32) s += sval[g][e];
        #pragma unroll
        for (int o = 16; o > 0; o >>= 1)
            s += __shfl_xor_sync(0xffffffffu, s, o);
        if (lt == 0) bsum[g] = s;
    }
    __syncthreads();
    if (lt < cnt) {
        g_selidx[(long)rowid*SELCAP + lt] = sidx[g][lt];
        g_selw  [(long)rowid*SELCAP + lt] = sval[g][lt] / bsum[g];
    }
    if (lt == 0) g_selcnt[rowid] = cnt;
}

// =============================================================================
// sparse_av8: 2x4 query tile, union gather; weights pre-duplicated as u64
// =============================================================================
__global__ void __launch_bounds__(256) sparse_av8(
    const float* __restrict__ v_cached, const float* __restrict__ vout)
{
    int chunk = blockIdx.x;
    int tile  = blockIdx.y;
    int z     = blockIdx.z;
    int b = z / NFtot, f = z % NFtot;
    int qy0 = (tile / 12) * 2, qx0 = (tile % 12) * 4;
    int tid = threadIdx.x;

    __shared__ int   sidx[8][SELCAP];
    __shared__ float sval[8][SELCAP];
    __shared__ int   scnt[8];
    __shared__ unsigned umask[72];
    __shared__ int   ubase[73];
    __shared__ int   uidx[MAXU];
    __shared__ u64   Wt2[8][MAXU];

    if (tid < 72) umask[tid] = 0;
    int rowbase = z * Ntok;
    if (tid < 8) {
        int q = tid;
        int n = (qy0 + (q >> 2)) * HGd + qx0 + (q & 3);
        scnt[q] = g_selcnt[rowbase + n];
    }
    __syncthreads();
    for (int i = tid; i < 8 * SELCAP; i += 256) {
        int q = i >> 6, e = i & (SELCAP-1);
        if (e < scnt[q]) {
            int n = (qy0 + (q >> 2)) * HGd + qx0 + (q & 3);
            long base = (long)(rowbase + n) * SELCAP + e;
            int m = g_selidx[base];
            sidx[q][e] = m;
            sval[q][e] = g_selw[base];
            atomicOr(&umask[m >> 5], 1u << (m & 31));
        }
    }
    __syncthreads();
    if (tid == 0) {
        int s = 0;
        for (int w = 0; w < 72; w++) { ubase[w] = s; s += __popc(umask[w]); }
        ubase[72] = s;
    }
    __syncthreads();
    int U = min(ubase[72], MAXU);

    for (int i = tid; i < 8*MAXU; i += 256) ((u64*)Wt2)[i] = 0ull;
    __syncthreads();
    if (tid < 72) {
        unsigned bits = umask[tid];
        int pos = ubase[tid];
        while (bits) {
            int bit = __ffs(bits) - 1; bits &= bits - 1;
            if (pos < MAXU) uidx[pos] = tid*32 + bit;
            pos++;
        }
    }
    __syncthreads();
    for (int i = tid; i < 8*SELCAP; i += 256) {
        int q = i >> 6, e = i & (SELCAP-1);
        if (e < scnt[q]) {
            int m = sidx[q][e];
            int w32 = m >> 5, bit = m & 31;
            int rank = ubase[w32] + __popc(umask[w32] & ((1u << bit) - 1u));
            if (rank < MAXU) Wt2[q][rank] = dup2(sval[q][e]);
        }
    }
    __syncthreads();

    const float* vbase = (f < 2) ? (v_cached + ((long)(b*2 + f)) * Ntok * VDdim)
                                 : (vout     + ((long)(b*2 + 1)) * Ntok * VDdim);
    int d0 = chunk * 1024 + tid * 4;
    u64 acc[8][2] = {};
    for (int e = 0; e < U; e++) {
        int m = uidx[e];
        ulonglong2 vv = *(const ulonglong2*)(vbase + (long)m * VDdim + d0);
        #pragma unroll
        for (int q = 0; q < 8; q++) {
            u64 wq = Wt2[q][e];
            fma2(acc[q][0], wq, vv.x);
            fma2(acc[q][1], wq, vv.y);
        }
    }
    #pragma unroll
    for (int q = 0; q < 8; q++) {
        int n = (qy0 + (q >> 2)) * HGd + qx0 + (q & 3);
        float2 p0 = unpk(acc[q][0]), p1 = unpk(acc[q][1]);
        float* orow = g_otok + ((long)(rowbase + n)) * VDdim + d0;
        *(float4*)orow = make_float4(p0.x, p0.y, p1.x, p1.y);
    }
}

// ---------------------------------- launch -----------------------------------
extern "C" void kernel_launch(void* const* d_in, const int* in_sizes, int n_in,
                              void* d_out, int out_size)
{
    (void)in_sizes; (void)n_in; (void)out_size;
    const float* x         = (const float*)d_in[0];
    const float* k_cached  = (const float*)d_in[1];
    const float* v_cached  = (const float*)d_in[2];
    const float* temperature = (const float*)d_in[3];
    const float* qk_w  = (const float*)d_in[4],  *qk_b  = (const float*)d_in[5];
    const float* qk_dw_w = (const float*)d_in[6], *qk_dw_b = (const float*)d_in[7];
    const float* v_w   = (const float*)d_in[8],  *v_b   = (const float*)d_in[9];
    const float* v_dw_w = (const float*)d_in[10], *v_dw_b = (const float*)d_in[11];
    const float* k2_w  = (const float*)d_in[12], *k2_b  = (const float*)d_in[13];
    const float* k2_dw_w = (const float*)d_in[14], *k2_dw_b = (const float*)d_in[15];
    const float* q2_w  = (const float*)d_in[16], *q2_b  = (const float*)d_in[17];
    const float* q2_dw_w = (const float*)d_in[18], *q2_dw_b = (const float*)d_in[19];
    const float* proj_w = (const float*)d_in[20], *proj_b = (const float*)d_in[21];

    float* out = (float*)d_out;
    const long OUT_K = (long)BATCH * NFtot * 128 * HW2;
    const long OUT_V = OUT_K + (long)BATCH * 2 * Ntok * D2;
    float* kout = out + OUT_K;
    float* vout = out + OUT_V;

    dim3 blk(256);

    static int attr_set = 0;
    if (!attr_set) {
        cudaFuncSetAttribute(gemm_stageA, cudaFuncAttributeMaxDynamicSharedMemorySize, CONV_SMEM);
        cudaFuncSetAttribute(gemm_stageC, cudaFuncAttributeMaxDynamicSharedMemorySize, CONV_SMEM);
        cudaFuncSetAttribute(attn_gemm2,  cudaFuncAttributeMaxDynamicSharedMemorySize, TT_SMEM);
        cudaFuncSetAttribute(proj_gemm2,  cudaFuncAttributeMaxDynamicSharedMemorySize, TT_SMEM);
        attr_set = 1;
    }

    gemm_stageA<<<dim3(288,3,BATCH), blk, CONV_SMEM>>>(x, qk_w, qk_b, v_w, v_b);
    dw3x3v<<<(BATCH*384*HW2/4 + 255)/256, blk>>>(qk_dw_w, qk_dw_b, v_dw_w, v_dw_b);
    gemm_stageC<<<dim3(288,4,BATCH), blk, CONV_SMEM>>>(q2_w, q2_b, k2_w, k2_b);
    dw4x4<<<(BATCH*512*Ntok + 255)/256, blk>>>(q2_dw_w, q2_dw_b, k2_dw_w, k2_dw_b);
    norm_qk<<<dim3(Ntok, BATCH), blk>>>(kout, temperature);
    build_vnew_t<<<dim3(HGd, 16, BATCH), blk>>>(vout);
    for (int b = 0; b < BATCH; b++) {
        cudaMemcpyAsync(kout + (long)(b*2)*Ntok*D2,
                        k_cached + (long)(b*2+1)*Ntok*D2,
                        (size_t)Ntok*D2*sizeof(float), cudaMemcpyDeviceToDevice, 0);
        cudaMemcpyAsync(vout + (long)(b*2)*Ntok*VDdim,
                        v_cached + (long)(b*2+1)*Ntok*VDdim,
                        (size_t)Ntok*VDdim*sizeof(float), cudaMemcpyDeviceToDevice, 0);
    }
    attn_gemm2<<<dim3(18,18,BATCH*NFtot), blk, TT_SMEM>>>(k_cached, kout);
    sparse_select4<<<dim3(Ntok/4, NFtot, BATCH), blk>>>();
    sparse_av8<<<dim3(2, 288, BATCH*NFtot), blk>>>(v_cached, vout);
    proj_gemm2<<<dim3(288,1,BATCH*NFtot), blk, TT_SMEM>>>(proj_w, proj_b, out);
}